// round 4
// baseline (speedup 1.0000x reference)
#include <cuda_runtime.h>
#include <cuda_bf16.h>
#include <math.h>
#include <stdint.h>

// Problem dims (fixed)
#define Dm   1024
#define Hh   16
#define DH   64
#define Rr   32
#define Bb   2
#define Ss   2048
#define BS   (Bb*Ss)        // 4096
#define HR   (Hh*Rr)        // 512
#define Ii   4096
#define RFC  512

// ---------------- scratch ----------------
__device__ float g_x [BS*Dm];
__device__ float g_Pq[BS*HR];
__device__ float g_Pk[BS*HR];
__device__ float g_Pv[BS*HR];
__device__ float g_Q [Bb*Hh*Ss*DH];
__device__ float g_K [Bb*Hh*Ss*DH];
__device__ float g_V [Bb*Hh*Ss*DH];
__device__ float g_Y [BS*Dm];
__device__ float g_t [BS*RFC];
__device__ float g_h [BS*Dm];
__device__ float g_a [BS*Ii];

// ---------------- common PTX helpers ----------------
__device__ __forceinline__ void cp16(uint32_t saddr, const void* gptr) {
    asm volatile("cp.async.ca.shared.global [%0], [%1], 16;" :: "r"(saddr), "l"(gptr));
}
// tf32 mma ignores the low 13 mantissa bits: raw fp32 bits are a valid operand.
__device__ __forceinline__ void mma_tf32(float* d, const uint32_t* a, const uint32_t* b) {
    asm volatile(
        "mma.sync.aligned.m16n8k8.row.col.f32.tf32.tf32.f32 "
        "{%0,%1,%2,%3}, {%4,%5,%6,%7}, {%8,%9}, {%0,%1,%2,%3};"
        : "+f"(d[0]), "+f"(d[1]), "+f"(d[2]), "+f"(d[3])
        : "r"(a[0]), "r"(a[1]), "r"(a[2]), "r"(a[3]), "r"(b[0]), "r"(b[1]));
}
__device__ __forceinline__ float gelu_tanh(float x) {
    float x3 = x * x * x;
    return 0.5f * x * (1.f + tanhf(0.7978845608f * (x + 0.044715f * x3)));
}

// ---------------- LayerNorm ----------------
__global__ void ln_kernel(const float* __restrict__ in, const float* __restrict__ w,
                          const float* __restrict__ b, float* __restrict__ out) {
    __shared__ float xs[Dm];
    __shared__ float red[8];
    int row = blockIdx.x;
    int t = threadIdx.x;
    const float* x = in + (size_t)row * Dm;

    float s = 0.f;
    #pragma unroll
    for (int i = t; i < Dm; i += 256) { float v = x[i]; xs[i] = v; s += v; }
    #pragma unroll
    for (int o = 16; o; o >>= 1) s += __shfl_xor_sync(0xffffffffu, s, o);
    if ((t & 31) == 0) red[t >> 5] = s;
    __syncthreads();
    float tot = 0.f;
    #pragma unroll
    for (int i = 0; i < 8; i++) tot += red[i];
    float mean = tot * (1.0f / Dm);
    __syncthreads();

    float vs = 0.f;
    #pragma unroll
    for (int i = t; i < Dm; i += 256) { float d = xs[i] - mean; vs += d * d; }
    #pragma unroll
    for (int o = 16; o; o >>= 1) vs += __shfl_xor_sync(0xffffffffu, vs, o);
    if ((t & 31) == 0) red[t >> 5] = vs;
    __syncthreads();
    float vtot = 0.f;
    #pragma unroll
    for (int i = 0; i < 8; i++) vtot += red[i];
    float rstd = rsqrtf(vtot * (1.0f / Dm) + 1e-5f);

    #pragma unroll
    for (int i = t; i < Dm; i += 256)
        out[(size_t)row * Dm + i] = (xs[i] - mean) * rstd * w[i] + b[i];
}

// ---------------- TF32 tensor-core GEMM (bitcast operands, no CVT) ----------------
template<int EPI, int BN>
__device__ __forceinline__ void gemm_core(
    const float* __restrict__ A, const float* __restrict__ B, float* __restrict__ C,
    int M, int N, int K, const float* __restrict__ bias, const float* __restrict__ res,
    int m0, int n0)
{
    constexpr int BM = 128, BK = 16;
    constexpr int WM_ = (BN == 128) ? 2 : 4;
    constexpr int WTM = BM / WM_;
    constexpr int WTN = BN / (8 / WM_);
    constexpr int MT = WTM / 16;
    constexpr int NT = WTN / 8;

    __shared__ __align__(16) float As[2][BM][BK + 4];
    __shared__ __align__(16) float Bs[2][BK][BN + 8];

    int tid = threadIdx.x;
    int w = tid >> 5, lane = tid & 31;
    int lr = lane >> 2, lc = lane & 3;
    int wm = (w % WM_) * WTM;
    int wn = (w / WM_) * WTN;

    float acc[MT][NT][4];
    #pragma unroll
    for (int mt = 0; mt < MT; mt++)
        #pragma unroll
        for (int nt = 0; nt < NT; nt++)
            #pragma unroll
            for (int i = 0; i < 4; i++) acc[mt][nt][i] = 0.f;

    const float* Ag = A + (size_t)m0 * K;
    const float* Bg = B + n0;

    auto loadTile = [&](int kt, int buf) {
        int k0 = kt * BK;
        #pragma unroll
        for (int i = 0; i < 2; i++) {
            int q = tid * 2 + i;
            int m = q >> 2, c = q & 3;
            uint32_t s = (uint32_t)__cvta_generic_to_shared(&As[buf][m][c * 4]);
            cp16(s, Ag + (size_t)m * K + k0 + c * 4);
        }
        #pragma unroll
        for (int i = 0; i < BN / 64; i++) {
            int q = tid + i * 256;
            int k = q / (BN / 4), n4 = q % (BN / 4);
            uint32_t s = (uint32_t)__cvta_generic_to_shared(&Bs[buf][k][n4 * 4]);
            cp16(s, Bg + (size_t)(k0 + k) * N + n4 * 4);
        }
        asm volatile("cp.async.commit_group;");
    };

    int NTILES = K / BK;
    loadTile(0, 0);
    for (int kt = 0; kt < NTILES; kt++) {
        int buf = kt & 1;
        if (kt + 1 < NTILES) {
            loadTile(kt + 1, buf ^ 1);
            asm volatile("cp.async.wait_group 1;");
        } else {
            asm volatile("cp.async.wait_group 0;");
        }
        __syncthreads();

        #pragma unroll
        for (int ks = 0; ks < 2; ks++) {
            int kb = ks * 8;
            uint32_t af[MT][4], bf[NT][2];
            #pragma unroll
            for (int mt = 0; mt < MT; mt++) {
                int r = wm + mt * 16 + lr;
                af[mt][0] = __float_as_uint(As[buf][r][kb + lc]);
                af[mt][1] = __float_as_uint(As[buf][r + 8][kb + lc]);
                af[mt][2] = __float_as_uint(As[buf][r][kb + lc + 4]);
                af[mt][3] = __float_as_uint(As[buf][r + 8][kb + lc + 4]);
            }
            #pragma unroll
            for (int nt = 0; nt < NT; nt++) {
                int cn = wn + nt * 8 + lr;
                bf[nt][0] = __float_as_uint(Bs[buf][kb + lc][cn]);
                bf[nt][1] = __float_as_uint(Bs[buf][kb + lc + 4][cn]);
            }
            #pragma unroll
            for (int mt = 0; mt < MT; mt++)
                #pragma unroll
                for (int nt = 0; nt < NT; nt++)
                    mma_tf32(acc[mt][nt], af[mt], bf[nt]);
        }
        __syncthreads();
    }

    #pragma unroll
    for (int mt = 0; mt < MT; mt++) {
        #pragma unroll
        for (int h = 0; h < 2; h++) {
            int row = m0 + wm + mt * 16 + lr + h * 8;
            #pragma unroll
            for (int nt = 0; nt < NT; nt++) {
                int col = n0 + wn + nt * 8 + 2 * lc;
                float v0 = acc[mt][nt][2 * h + 0];
                float v1 = acc[mt][nt][2 * h + 1];
                if (EPI == 1) {
                    v0 += bias[col]     + res[(size_t)row * N + col];
                    v1 += bias[col + 1] + res[(size_t)row * N + col + 1];
                } else if (EPI == 2) {
                    v0 = gelu_tanh(v0 + bias[col]);
                    v1 = gelu_tanh(v1 + bias[col + 1]);
                }
                *(float2*)&C[(size_t)row * N + col] = make_float2(v0, v1);
            }
        }
    }
}

template<int EPI, int BN>
__global__ void __launch_bounds__(256, 2) sgemm_t(
    const float* __restrict__ A, const float* __restrict__ B, float* __restrict__ C,
    int M, int N, int K, const float* __restrict__ bias, const float* __restrict__ res)
{
    gemm_core<EPI, BN>(A, B, C, M, N, K, bias, res, blockIdx.y * 128, blockIdx.x * BN);
}

__global__ void __launch_bounds__(256, 2) sgemm_qkv(
    const float* __restrict__ A,
    const float* __restrict__ B0, const float* __restrict__ B1, const float* __restrict__ B2,
    float* __restrict__ C0, float* __restrict__ C1, float* __restrict__ C2,
    int M, int N, int K)
{
    int sel = blockIdx.x >> 2, nb = blockIdx.x & 3;
    const float* B = (sel == 0) ? B0 : (sel == 1) ? B1 : B2;
    float* C = (sel == 0) ? C0 : (sel == 1) ? C1 : C2;
    gemm_core<0, 128>(A, B, C, M, N, K, nullptr, nullptr, blockIdx.y * 128, nb * 128);
}

// ---------------- head_proj v2 ----------------
__global__ void __launch_bounds__(256) head_proj2(
    const float* __restrict__ Pq, const float* __restrict__ Pk, const float* __restrict__ Pv,
    const float* __restrict__ Vq, const float* __restrict__ Vk, const float* __restrict__ Vv,
    const float* __restrict__ bq, const float* __restrict__ bk, const float* __restrict__ bv,
    float* __restrict__ Oq, float* __restrict__ Ok, float* __restrict__ Ov)
{
    __shared__ float vw[Rr][DH];
    __shared__ float pt[64][Rr + 1];
    int z = blockIdx.z;
    const float* P  = (z == 0) ? Pq : (z == 1) ? Pk : Pv;
    const float* Vw = (z == 0) ? Vq : (z == 1) ? Vk : Vv;
    const float* bi = (z == 0) ? bq : (z == 1) ? bk : bv;
    float* O        = (z == 0) ? Oq : (z == 1) ? Ok : Ov;

    int h = blockIdx.y;
    int s0 = blockIdx.x * 64;
    int tid = threadIdx.x;

    #pragma unroll
    for (int i = 0; i < 8; i++) {
        int idx = tid + i * 256;
        vw[idx >> 6][idx & 63] = Vw[(size_t)h * Rr * DH + idx];
    }
    #pragma unroll
    for (int i = 0; i < 8; i++) {
        int idx = tid + i * 256;
        int r = idx >> 5, c = idx & 31;
        pt[r][c] = P[(size_t)(s0 + r) * HR + h * Rr + c];
    }
    __syncthreads();

    int e = tid & 63;
    int sl = tid >> 6;
    float bv_ = bi[h * DH + e];
    #pragma unroll
    for (int i = 0; i < 16; i++) {
        int r = sl + i * 4;
        float acc = bv_;
        #pragma unroll
        for (int rr = 0; rr < Rr; rr++) acc = fmaf(pt[r][rr], vw[rr][e], acc);
        int bs = s0 + r;
        int b = bs >> 11, s = bs & 2047;
        O[(((size_t)(b * Hh + h)) * Ss + s) * DH + e] = acc;
    }
}

// ---------------- attention v3: 128 queries/CTA, 8 warps, cp.async, no CVT ----------------
#define KSd 68
#define VSd 72
#define PSd 68
#define ATTN_SMEM ((64*KSd + 64*VSd + 128*PSd) * 4)   // 70656 B

__global__ void __launch_bounds__(256) attn_mma2(
    const float* __restrict__ Q, const float* __restrict__ K,
    const float* __restrict__ V, float* __restrict__ Y)
{
    extern __shared__ uint32_t sm[];
    uint32_t* Ks = sm;                       // [64][KSd]
    uint32_t* Vs = sm + 64 * KSd;            // [64][VSd]
    uint32_t* Ps = sm + 64 * KSd + 64 * VSd; // [128][PSd]

    int bh = blockIdx.y;
    int qblk = gridDim.x - 1 - blockIdx.x;   // heavy blocks first
    int q0 = qblk * 128;
    int tid = threadIdx.x;
    int w = tid >> 5, lane = tid & 31;
    int lr = lane >> 2, lc = lane & 3;
    int wq = w * 16;

    // persistent Q fragments (raw fp32 bits)
    uint32_t qf[8][4];
    const float* Qb = Q + ((size_t)bh * Ss + q0 + wq) * DH;
    #pragma unroll
    for (int ks = 0; ks < 8; ks++) {
        qf[ks][0] = __float_as_uint(Qb[(size_t)lr * DH + ks * 8 + lc]);
        qf[ks][1] = __float_as_uint(Qb[(size_t)(lr + 8) * DH + ks * 8 + lc]);
        qf[ks][2] = __float_as_uint(Qb[(size_t)lr * DH + ks * 8 + lc + 4]);
        qf[ks][3] = __float_as_uint(Qb[(size_t)(lr + 8) * DH + ks * 8 + lc + 4]);
    }

    float o[8][4];
    #pragma unroll
    for (int nt = 0; nt < 8; nt++)
        #pragma unroll
        for (int i = 0; i < 4; i++) o[nt][i] = 0.f;
    float m0 = -1e30f, m1 = -1e30f, l0 = 0.f, l1 = 0.f;
    const float scale = 0.125f;

    int ktmax = 2 * qblk + 1;
    for (int kt = 0; kt <= ktmax; kt++) {
        const float* kb_ = K + ((size_t)bh * Ss + kt * 64) * DH;
        const float* vb_ = V + ((size_t)bh * Ss + kt * 64) * DH;
        __syncthreads();
        #pragma unroll
        for (int i = 0; i < 4; i++) {            // 1024 chunks: K + V
            int idx = tid + i * 256;
            int r = idx >> 4, c4 = (idx & 15) * 4;
            cp16((uint32_t)__cvta_generic_to_shared(&Ks[r * KSd + c4]),
                 kb_ + (size_t)r * DH + c4);
            cp16((uint32_t)__cvta_generic_to_shared(&Vs[r * VSd + c4]),
                 vb_ + (size_t)r * DH + c4);
        }
        asm volatile("cp.async.commit_group;");
        asm volatile("cp.async.wait_group 0;");
        __syncthreads();

        // S = Q @ K^T   (per warp 16 x 64)
        float s[8][4];
        #pragma unroll
        for (int nt = 0; nt < 8; nt++)
            #pragma unroll
            for (int i = 0; i < 4; i++) s[nt][i] = 0.f;
        #pragma unroll
        for (int ks = 0; ks < 8; ks++) {
            #pragma unroll
            for (int nt = 0; nt < 8; nt++) {
                uint32_t bf[2];
                bf[0] = Ks[(nt * 8 + lr) * KSd + ks * 8 + lc];
                bf[1] = Ks[(nt * 8 + lr) * KSd + ks * 8 + lc + 4];
                mma_tf32(s[nt], qf[ks], bf);
            }
        }

        // scale + causal mask
        bool diag = (kt >= 2 * qblk);
        int r0 = q0 + wq + lr, r1 = r0 + 8;
        int kc0 = kt * 64;
        #pragma unroll
        for (int nt = 0; nt < 8; nt++) {
            int c0 = kc0 + nt * 8 + 2 * lc, c1 = c0 + 1;
            s[nt][0] = (diag && c0 > r0) ? -1e30f : s[nt][0] * scale;
            s[nt][1] = (diag && c1 > r0) ? -1e30f : s[nt][1] * scale;
            s[nt][2] = (diag && c0 > r1) ? -1e30f : s[nt][2] * scale;
            s[nt][3] = (diag && c1 > r1) ? -1e30f : s[nt][3] * scale;
        }

        // row max (quad reduce)
        float mx0 = -1e30f, mx1 = -1e30f;
        #pragma unroll
        for (int nt = 0; nt < 8; nt++) {
            mx0 = fmaxf(mx0, fmaxf(s[nt][0], s[nt][1]));
            mx1 = fmaxf(mx1, fmaxf(s[nt][2], s[nt][3]));
        }
        mx0 = fmaxf(mx0, __shfl_xor_sync(0xffffffffu, mx0, 1));
        mx0 = fmaxf(mx0, __shfl_xor_sync(0xffffffffu, mx0, 2));
        mx1 = fmaxf(mx1, __shfl_xor_sync(0xffffffffu, mx1, 1));
        mx1 = fmaxf(mx1, __shfl_xor_sync(0xffffffffu, mx1, 2));
        float mn0 = fmaxf(m0, mx0), mn1 = fmaxf(m1, mx1);
        float c0f = __expf(m0 - mn0), c1f = __expf(m1 - mn1);
        l0 *= c0f; l1 *= c1f;
        #pragma unroll
        for (int nt = 0; nt < 8; nt++) {
            o[nt][0] *= c0f; o[nt][1] *= c0f;
            o[nt][2] *= c1f; o[nt][3] *= c1f;
        }
        m0 = mn0; m1 = mn1;

        // P = exp(s - m) -> per-warp private smem region (no block sync needed)
        #pragma unroll
        for (int nt = 0; nt < 8; nt++) {
            int c0 = nt * 8 + 2 * lc;
            float p00 = __expf(s[nt][0] - mn0);
            float p01 = __expf(s[nt][1] - mn0);
            float p10 = __expf(s[nt][2] - mn1);
            float p11 = __expf(s[nt][3] - mn1);
            l0 += p00 + p01; l1 += p10 + p11;
            Ps[(wq + lr) * PSd + c0]     = __float_as_uint(p00);
            Ps[(wq + lr) * PSd + c0 + 1] = __float_as_uint(p01);
            Ps[(wq + lr + 8) * PSd + c0]     = __float_as_uint(p10);
            Ps[(wq + lr + 8) * PSd + c0 + 1] = __float_as_uint(p11);
        }
        __syncwarp();

        // O += P @ V
        #pragma unroll
        for (int ks = 0; ks < 8; ks++) {
            uint32_t pa[4];
            pa[0] = Ps[(wq + lr) * PSd + ks * 8 + lc];
            pa[1] = Ps[(wq + lr + 8) * PSd + ks * 8 + lc];
            pa[2] = Ps[(wq + lr) * PSd + ks * 8 + lc + 4];
            pa[3] = Ps[(wq + lr + 8) * PSd + ks * 8 + lc + 4];
            #pragma unroll
            for (int nt = 0; nt < 8; nt++) {
                uint32_t bf[2];
                bf[0] = Vs[(ks * 8 + lc) * VSd + nt * 8 + lr];
                bf[1] = Vs[(ks * 8 + lc + 4) * VSd + nt * 8 + lr];
                mma_tf32(o[nt], pa, bf);
            }
        }
    }

    // epilogue
    l0 += __shfl_xor_sync(0xffffffffu, l0, 1);
    l0 += __shfl_xor_sync(0xffffffffu, l0, 2);
    l1 += __shfl_xor_sync(0xffffffffu, l1, 1);
    l1 += __shfl_xor_sync(0xffffffffu, l1, 2);
    float i0 = 1.f / l0, i1 = 1.f / l1;
    int b = bh >> 4, h = bh & 15;
    int row0 = q0 + wq + lr, row1 = row0 + 8;
    float* y0 = Y + (((size_t)(b * Ss + row0)) * Hh + h) * DH;
    float* y1 = Y + (((size_t)(b * Ss + row1)) * Hh + h) * DH;
    #pragma unroll
    for (int nt = 0; nt < 8; nt++) {
        int c = nt * 8 + 2 * lc;
        *(float2*)(y0 + c) = make_float2(o[nt][0] * i0, o[nt][1] * i0);
        *(float2*)(y1 + c) = make_float2(o[nt][2] * i1, o[nt][3] * i1);
    }
}

// ---------------- launch ----------------
extern "C" void kernel_launch(void* const* d_in, const int* in_sizes, int n_in,
                              void* d_out, int out_size) {
    const float* hidden = (const float*)d_in[0];
    const float* ln1_w = (const float*)d_in[2];
    const float* ln1_b = (const float*)d_in[3];
    const float* q_U = (const float*)d_in[4];
    const float* q_V = (const float*)d_in[5];
    const float* q_b = (const float*)d_in[6];
    const float* k_U = (const float*)d_in[7];
    const float* k_V = (const float*)d_in[8];
    const float* k_b = (const float*)d_in[9];
    const float* v_U = (const float*)d_in[10];
    const float* v_V = (const float*)d_in[11];
    const float* v_b = (const float*)d_in[12];
    const float* out_U = (const float*)d_in[13];
    const float* out_V = (const float*)d_in[14];
    const float* out_b = (const float*)d_in[15];
    const float* ln2_w = (const float*)d_in[16];
    const float* ln2_b = (const float*)d_in[17];
    const float* fc1_U = (const float*)d_in[18];
    const float* fc1_V = (const float*)d_in[19];
    const float* fc1_b = (const float*)d_in[20];
    const float* fc2_U = (const float*)d_in[21];
    const float* fc2_V = (const float*)d_in[22];
    const float* fc2_b = (const float*)d_in[23];
    float* out = (float*)d_out;

    float *x_, *Pq_, *Pk_, *Pv_, *Q_, *K_, *V_, *Y_, *t_, *h_, *a_;
    cudaGetSymbolAddress((void**)&x_,  g_x);
    cudaGetSymbolAddress((void**)&Pq_, g_Pq);
    cudaGetSymbolAddress((void**)&Pk_, g_Pk);
    cudaGetSymbolAddress((void**)&Pv_, g_Pv);
    cudaGetSymbolAddress((void**)&Q_,  g_Q);
    cudaGetSymbolAddress((void**)&K_,  g_K);
    cudaGetSymbolAddress((void**)&V_,  g_V);
    cudaGetSymbolAddress((void**)&Y_,  g_Y);
    cudaGetSymbolAddress((void**)&t_,  g_t);
    cudaGetSymbolAddress((void**)&h_,  g_h);
    cudaGetSymbolAddress((void**)&a_,  g_a);

    static bool attr_set = false;
    if (!attr_set) {
        cudaFuncSetAttribute(attn_mma2, cudaFuncAttributeMaxDynamicSharedMemorySize, ATTN_SMEM);
        attr_set = true;
    }

    // 1) x = LN1(hidden)
    ln_kernel<<<BS, 256>>>(hidden, ln1_w, ln1_b, x_);

    // 2) Pq/Pk/Pv = x @ {q,k,v}_U
    {
        dim3 g(12, BS / 128);
        sgemm_qkv<<<g, 256>>>(x_, q_U, k_U, v_U, Pq_, Pk_, Pv_, BS, HR, Dm);
    }

    // 3) head expansion
    {
        dim3 g(BS / 64, Hh, 3);
        head_proj2<<<g, 256>>>(Pq_, Pk_, Pv_, q_V, k_V, v_V, q_b, k_b, v_b, Q_, K_, V_);
    }

    // 4) causal attention
    {
        dim3 g(Ss / 128, Bb * Hh);
        attn_mma2<<<g, 256, ATTN_SMEM>>>(Q_, K_, V_, Y_);
    }

    // 5) h = hidden + (Y @ out_U) @ out_V + out_b
    {
        dim3 g1(RFC / 64, BS / 128);
        sgemm_t<0, 64><<<g1, 256>>>(Y_, out_U, t_, BS, RFC, Dm, nullptr, nullptr);
        dim3 g2(Dm / 128, BS / 128);
        sgemm_t<1, 128><<<g2, 256>>>(t_, out_V, h_, BS, Dm, RFC, out_b, hidden);
    }

    // 6) z = LN2(h)
    ln_kernel<<<BS, 256>>>(h_, ln2_w, ln2_b, x_);

    // 7) a = gelu((z @ fc1_U) @ fc1_V + fc1_b)
    {
        dim3 g1(RFC / 64, BS / 128);
        sgemm_t<0, 64><<<g1, 256>>>(x_, fc1_U, t_, BS, RFC, Dm, nullptr, nullptr);
        dim3 g2(Ii / 128, BS / 128);
        sgemm_t<2, 128><<<g2, 256>>>(t_, fc1_V, a_, BS, Ii, RFC, fc1_b, nullptr);
    }

    // 8) out = h + (a @ fc2_U) @ fc2_V + fc2_b
    {
        dim3 g1(RFC / 64, BS / 128);
        sgemm_t<0, 64><<<g1, 256>>>(a_, fc2_U, t_, BS, RFC, Ii, nullptr, nullptr);
        dim3 g2(Dm / 128, BS / 128);
        sgemm_t<1, 128><<<g2, 256>>>(t_, fc2_V, out, BS, Dm, RFC, fc2_b, h_);
    }
}

// round 5
// speedup vs baseline: 1.0050x; 1.0050x over previous
#include <cuda_runtime.h>
#include <cuda_bf16.h>
#include <math.h>
#include <stdint.h>

// Problem dims (fixed)
#define Dm   1024
#define Hh   16
#define DH   64
#define Rr   32
#define Bb   2
#define Ss   2048
#define BS   (Bb*Ss)        // 4096
#define HR   (Hh*Rr)        // 512
#define Ii   4096
#define RFC  512

// ---------------- scratch ----------------
__device__ float g_x [BS*Dm];
__device__ float g_Pq[BS*HR];
__device__ float g_Pk[BS*HR];
__device__ float g_Pv[BS*HR];
__device__ float g_Q [Bb*Hh*Ss*DH];
__device__ float g_K [Bb*Hh*Ss*DH];
__device__ float g_V [Bb*Hh*DH*Ss];   // V stored TRANSPOSED: [b,h,dh,s]
__device__ float g_Y [BS*Dm];
__device__ float g_t [BS*RFC];
__device__ float g_h [BS*Dm];
__device__ float g_a [BS*Ii];

// ---------------- PTX helpers ----------------
__device__ __forceinline__ void cp16(uint32_t saddr, const void* gptr) {
    asm volatile("cp.async.ca.shared.global [%0], [%1], 16;" :: "r"(saddr), "l"(gptr));
}
__device__ __forceinline__ uint32_t smem_u32(const void* p) {
    return (uint32_t)__cvta_generic_to_shared(p);
}
__device__ __forceinline__ void ldsm4(uint32_t& r0, uint32_t& r1, uint32_t& r2, uint32_t& r3,
                                      uint32_t addr) {
    asm volatile("ldmatrix.sync.aligned.m8n8.x4.shared.b16 {%0,%1,%2,%3}, [%4];"
                 : "=r"(r0), "=r"(r1), "=r"(r2), "=r"(r3) : "r"(addr));
}
// tf32 mma ignores low 13 mantissa bits: raw fp32 bits are a valid operand.
__device__ __forceinline__ void mma_tf32(float* d, const uint32_t* a, const uint32_t* b) {
    asm volatile(
        "mma.sync.aligned.m16n8k8.row.col.f32.tf32.tf32.f32 "
        "{%0,%1,%2,%3}, {%4,%5,%6,%7}, {%8,%9}, {%0,%1,%2,%3};"
        : "+f"(d[0]), "+f"(d[1]), "+f"(d[2]), "+f"(d[3])
        : "r"(a[0]), "r"(a[1]), "r"(a[2]), "r"(a[3]), "r"(b[0]), "r"(b[1]));
}
__device__ __forceinline__ float gelu_tanh(float x) {
    float u = 0.7978845608f * (x + 0.044715f * x * x * x);
    float t = 1.f - 2.f / (__expf(2.f * u) + 1.f);     // tanh via expf
    return 0.5f * x * (1.f + t);
}

// ---------------- LayerNorm ----------------
__global__ void ln_kernel(const float* __restrict__ in, const float* __restrict__ w,
                          const float* __restrict__ b, float* __restrict__ out) {
    __shared__ float xs[Dm];
    __shared__ float red[8];
    int row = blockIdx.x;
    int t = threadIdx.x;
    const float* x = in + (size_t)row * Dm;

    float s = 0.f;
    #pragma unroll
    for (int i = t; i < Dm; i += 256) { float v = x[i]; xs[i] = v; s += v; }
    #pragma unroll
    for (int o = 16; o; o >>= 1) s += __shfl_xor_sync(0xffffffffu, s, o);
    if ((t & 31) == 0) red[t >> 5] = s;
    __syncthreads();
    float tot = 0.f;
    #pragma unroll
    for (int i = 0; i < 8; i++) tot += red[i];
    float mean = tot * (1.0f / Dm);
    __syncthreads();

    float vs = 0.f;
    #pragma unroll
    for (int i = t; i < Dm; i += 256) { float d = xs[i] - mean; vs += d * d; }
    #pragma unroll
    for (int o = 16; o; o >>= 1) vs += __shfl_xor_sync(0xffffffffu, vs, o);
    if ((t & 31) == 0) red[t >> 5] = vs;
    __syncthreads();
    float vtot = 0.f;
    #pragma unroll
    for (int i = 0; i < 8; i++) vtot += red[i];
    float rstd = rsqrtf(vtot * (1.0f / Dm) + 1e-5f);

    #pragma unroll
    for (int i = t; i < Dm; i += 256)
        out[(size_t)row * Dm + i] = (xs[i] - mean) * rstd * w[i] + b[i];
}

// ---------------- TF32 GEMM, A-fragments via ldmatrix ----------------
template<int EPI, int BN>
__device__ __forceinline__ void gemm_core(
    const float* __restrict__ A, const float* __restrict__ B, float* __restrict__ C,
    int M, int N, int K, const float* __restrict__ bias, const float* __restrict__ res,
    int m0, int n0)
{
    constexpr int BM = 128, BK = 16;
    constexpr int WM_ = (BN == 128) ? 2 : 4;
    constexpr int WTM = BM / WM_;
    constexpr int WTN = BN / (8 / WM_);
    constexpr int MT = WTM / 16;
    constexpr int NT = WTN / 8;

    __shared__ __align__(16) float As[2][BM][BK + 4];   // stride 20 -> ldsm quads 5r%8 distinct
    __shared__ __align__(16) float Bs[2][BK][BN + 8];

    int tid = threadIdx.x;
    int w = tid >> 5, lane = tid & 31;
    int lr = lane >> 2, lc = lane & 3;
    int wm = (w % WM_) * WTM;
    int wn = (w / WM_) * WTN;
    int arow_f = (lane & 7) + ((lane >> 3) & 1) * 8;     // ldsm row-in-16
    int acol_f = (lane >> 4) * 4;                         // ldsm col chunk

    float acc[MT][NT][4];
    #pragma unroll
    for (int mt = 0; mt < MT; mt++)
        #pragma unroll
        for (int nt = 0; nt < NT; nt++)
            #pragma unroll
            for (int i = 0; i < 4; i++) acc[mt][nt][i] = 0.f;

    const float* Ag = A + (size_t)m0 * K;
    const float* Bg = B + n0;

    auto loadTile = [&](int kt, int buf) {
        int k0 = kt * BK;
        #pragma unroll
        for (int i = 0; i < 2; i++) {
            int q = tid * 2 + i;
            int m = q >> 2, c = q & 3;
            cp16(smem_u32(&As[buf][m][c * 4]), Ag + (size_t)m * K + k0 + c * 4);
        }
        #pragma unroll
        for (int i = 0; i < BN / 64; i++) {
            int q = tid + i * 256;
            int k = q / (BN / 4), n4 = q % (BN / 4);
            cp16(smem_u32(&Bs[buf][k][n4 * 4]), Bg + (size_t)(k0 + k) * N + n4 * 4);
        }
        asm volatile("cp.async.commit_group;");
    };

    int NTILES = K / BK;
    loadTile(0, 0);
    for (int kt = 0; kt < NTILES; kt++) {
        int buf = kt & 1;
        if (kt + 1 < NTILES) {
            loadTile(kt + 1, buf ^ 1);
            asm volatile("cp.async.wait_group 1;");
        } else {
            asm volatile("cp.async.wait_group 0;");
        }
        __syncthreads();

        #pragma unroll
        for (int ks = 0; ks < 2; ks++) {
            int kb = ks * 8;
            uint32_t af[MT][4], bf[NT][2];
            #pragma unroll
            for (int mt = 0; mt < MT; mt++)
                ldsm4(af[mt][0], af[mt][1], af[mt][2], af[mt][3],
                      smem_u32(&As[buf][wm + mt * 16 + arow_f][kb + acol_f]));
            #pragma unroll
            for (int nt = 0; nt < NT; nt++) {
                int cn = wn + nt * 8 + lr;
                bf[nt][0] = __float_as_uint(Bs[buf][kb + lc][cn]);
                bf[nt][1] = __float_as_uint(Bs[buf][kb + lc + 4][cn]);
            }
            #pragma unroll
            for (int mt = 0; mt < MT; mt++)
                #pragma unroll
                for (int nt = 0; nt < NT; nt++)
                    mma_tf32(acc[mt][nt], af[mt], bf[nt]);
        }
        __syncthreads();
    }

    #pragma unroll
    for (int mt = 0; mt < MT; mt++) {
        #pragma unroll
        for (int h = 0; h < 2; h++) {
            int row = m0 + wm + mt * 16 + lr + h * 8;
            #pragma unroll
            for (int nt = 0; nt < NT; nt++) {
                int col = n0 + wn + nt * 8 + 2 * lc;
                float v0 = acc[mt][nt][2 * h + 0];
                float v1 = acc[mt][nt][2 * h + 1];
                if (EPI == 1) {
                    v0 += bias[col]     + res[(size_t)row * N + col];
                    v1 += bias[col + 1] + res[(size_t)row * N + col + 1];
                } else if (EPI == 2) {
                    v0 = gelu_tanh(v0 + bias[col]);
                    v1 = gelu_tanh(v1 + bias[col + 1]);
                }
                *(float2*)&C[(size_t)row * N + col] = make_float2(v0, v1);
            }
        }
    }
}

template<int EPI, int BN>
__global__ void __launch_bounds__(256, 2) sgemm_t(
    const float* __restrict__ A, const float* __restrict__ B, float* __restrict__ C,
    int M, int N, int K, const float* __restrict__ bias, const float* __restrict__ res)
{
    gemm_core<EPI, BN>(A, B, C, M, N, K, bias, res, blockIdx.y * 128, blockIdx.x * BN);
}

__global__ void __launch_bounds__(256, 2) sgemm_qkv(
    const float* __restrict__ A,
    const float* __restrict__ B0, const float* __restrict__ B1, const float* __restrict__ B2,
    float* __restrict__ C0, float* __restrict__ C1, float* __restrict__ C2,
    int M, int N, int K)
{
    int sel = blockIdx.x >> 2, nb = blockIdx.x & 3;
    const float* B = (sel == 0) ? B0 : (sel == 1) ? B1 : B2;
    float* C = (sel == 0) ? C0 : (sel == 1) ? C1 : C2;
    gemm_core<0, 128>(A, B, C, M, N, K, nullptr, nullptr, blockIdx.y * 128, nb * 128);
}

// ---------------- head_proj: q,k -> (b,h,s,e); v -> TRANSPOSED (b,h,e,s) ----------------
__global__ void __launch_bounds__(256) head_proj2(
    const float* __restrict__ Pq, const float* __restrict__ Pk, const float* __restrict__ Pv,
    const float* __restrict__ Vq, const float* __restrict__ Vk, const float* __restrict__ Vv,
    const float* __restrict__ bq, const float* __restrict__ bk, const float* __restrict__ bv,
    float* __restrict__ Oq, float* __restrict__ Ok, float* __restrict__ Ov)
{
    __shared__ float vw[Rr][DH];
    __shared__ float pt[64][Rr + 1];
    int z = blockIdx.z;
    const float* P  = (z == 0) ? Pq : (z == 1) ? Pk : Pv;
    const float* Vw = (z == 0) ? Vq : (z == 1) ? Vk : Vv;
    const float* bi = (z == 0) ? bq : (z == 1) ? bk : bv;
    float* O        = (z == 0) ? Oq : (z == 1) ? Ok : Ov;

    int h = blockIdx.y;
    int s0 = blockIdx.x * 64;
    int tid = threadIdx.x;

    #pragma unroll
    for (int i = 0; i < 8; i++) {
        int idx = tid + i * 256;
        vw[idx >> 6][idx & 63] = Vw[(size_t)h * Rr * DH + idx];
    }
    #pragma unroll
    for (int i = 0; i < 8; i++) {
        int idx = tid + i * 256;
        int r = idx >> 5, c = idx & 31;
        pt[r][c] = P[(size_t)(s0 + r) * HR + h * Rr + c];
    }
    __syncthreads();

    if (z < 2) {
        int e = tid & 63;
        int sl = tid >> 6;
        float bv_ = bi[h * DH + e];
        #pragma unroll
        for (int i = 0; i < 16; i++) {
            int r = sl + i * 4;
            float acc = bv_;
            #pragma unroll
            for (int rr = 0; rr < Rr; rr++) acc = fmaf(pt[r][rr], vw[rr][e], acc);
            int bs = s0 + r;
            int b = bs >> 11, s = bs & 2047;
            O[(((size_t)(b * Hh + h)) * Ss + s) * DH + e] = acc;
        }
    } else {
        // V transposed: O[((b*Hh+h)*DH + e)*Ss + s]; lanes over s -> coalesced
        int sl = tid & 63;
        int e0 = tid >> 6;
        int bs = s0 + sl;
        int b = bs >> 11, s = bs & 2047;
        float* obase = O + ((size_t)(b * Hh + h)) * DH * Ss + s;
        #pragma unroll
        for (int i = 0; i < 16; i++) {
            int e = e0 + i * 4;
            float acc = bi[h * DH + e];
            #pragma unroll
            for (int rr = 0; rr < Rr; rr++) acc = fmaf(pt[sl][rr], vw[rr][e], acc);
            obase[(size_t)e * Ss] = acc;
        }
    }
}

// ---------------- attention v4: ldmatrix + double-buffered cp.async ----------------
#define ASd 68
#define ATTN_SMEM ((5 * 64 * ASd) * 4)   // 2xK + 2xVt + P(128 rows) = 5*64 rows of 68 -> 87040? see below
// Ks: 2 * 64*68, Vt: 2 * 64*68, Ps: 128*68  => (4*4352 + 8704) = 26112 words = 104448 bytes
#undef ATTN_SMEM
#define ATTN_SMEM (26112 * 4)

__global__ void __launch_bounds__(256) attn_mma3(
    const float* __restrict__ Q, const float* __restrict__ K,
    const float* __restrict__ V, float* __restrict__ Y)
{
    extern __shared__ uint32_t sm[];
    uint32_t* KsB[2] = { sm,               sm + 64 * ASd };
    uint32_t* VtB[2] = { sm + 2 * 64 * ASd, sm + 3 * 64 * ASd };
    uint32_t* Ps     =   sm + 4 * 64 * ASd;     // [128][ASd]

    int bh = blockIdx.y;
    int qblk = gridDim.x - 1 - blockIdx.x;       // heavy blocks first
    int q0 = qblk * 128;
    int tid = threadIdx.x;
    int w = tid >> 5, lane = tid & 31;
    int lr = lane >> 2, lc = lane & 3;
    int wq = w * 16;
    int frow = (lane & 7) + ((lane >> 3) & 1) * 8;   // A-frag ldsm row-in-16
    int fcol = (lane >> 4) * 4;                       // A-frag ldsm col chunk
    int brow = lane & 7;                              // B-frag ldsm row-in-8
    int bcol = (lane >> 3) * 4;                       // B-frag ldsm col chunk (4 chunks = 2 ks)

    // persistent Q fragments (raw fp32 bits)
    uint32_t qf[8][4];
    const float* Qb = Q + ((size_t)bh * Ss + q0 + wq) * DH;
    #pragma unroll
    for (int ks = 0; ks < 8; ks++) {
        qf[ks][0] = __float_as_uint(Qb[(size_t)lr * DH + ks * 8 + lc]);
        qf[ks][1] = __float_as_uint(Qb[(size_t)(lr + 8) * DH + ks * 8 + lc]);
        qf[ks][2] = __float_as_uint(Qb[(size_t)lr * DH + ks * 8 + lc + 4]);
        qf[ks][3] = __float_as_uint(Qb[(size_t)(lr + 8) * DH + ks * 8 + lc + 4]);
    }

    const float* Kg = K + (size_t)bh * Ss * DH;
    const float* Vg = V + (size_t)bh * DH * Ss;   // transposed layout [dh][s]

    auto loadTile = [&](int kt, int buf) {
        uint32_t* Ks = KsB[buf];
        uint32_t* Vt = VtB[buf];
        #pragma unroll
        for (int i = 0; i < 4; i++) {
            int idx = tid + i * 256;
            int r = idx >> 4, c4 = (idx & 15) * 4;
            cp16(smem_u32(Ks + r * ASd + c4), Kg + (size_t)(kt * 64 + r) * DH + c4);
            cp16(smem_u32(Vt + r * ASd + c4), Vg + (size_t)r * Ss + kt * 64 + c4);
        }
        asm volatile("cp.async.commit_group;");
    };

    float o[8][4];
    #pragma unroll
    for (int nt = 0; nt < 8; nt++)
        #pragma unroll
        for (int i = 0; i < 4; i++) o[nt][i] = 0.f;
    float m0 = -1e30f, m1 = -1e30f, l0 = 0.f, l1 = 0.f;
    const float scale = 0.125f;

    int ktmax = 2 * qblk + 1;
    loadTile(0, 0);
    for (int kt = 0; kt <= ktmax; kt++) {
        int buf = kt & 1;
        if (kt < ktmax) {
            loadTile(kt + 1, buf ^ 1);
            asm volatile("cp.async.wait_group 1;");
        } else {
            asm volatile("cp.async.wait_group 0;");
        }
        __syncthreads();
        uint32_t* Ks = KsB[buf];
        uint32_t* Vt = VtB[buf];

        // S = Q @ K^T (per warp 16x64): B-frags via ldmatrix.x4 (2 ks per load)
        float s[8][4];
        #pragma unroll
        for (int nt = 0; nt < 8; nt++)
            #pragma unroll
            for (int i = 0; i < 4; i++) s[nt][i] = 0.f;
        #pragma unroll
        for (int k2 = 0; k2 < 4; k2++) {
            #pragma unroll
            for (int nt = 0; nt < 8; nt++) {
                uint32_t b0, b1, b2, b3;
                ldsm4(b0, b1, b2, b3,
                      smem_u32(Ks + (nt * 8 + brow) * ASd + k2 * 16 + bcol));
                uint32_t bfa[2] = {b0, b1}, bfb[2] = {b2, b3};
                mma_tf32(s[nt], qf[2 * k2],     bfa);
                mma_tf32(s[nt], qf[2 * k2 + 1], bfb);
            }
        }

        // scale + causal mask
        bool diag = (kt >= 2 * qblk);
        int r0 = q0 + wq + lr, r1 = r0 + 8;
        int kc0 = kt * 64;
        #pragma unroll
        for (int nt = 0; nt < 8; nt++) {
            int c0 = kc0 + nt * 8 + 2 * lc, c1 = c0 + 1;
            s[nt][0] = (diag && c0 > r0) ? -1e30f : s[nt][0] * scale;
            s[nt][1] = (diag && c1 > r0) ? -1e30f : s[nt][1] * scale;
            s[nt][2] = (diag && c0 > r1) ? -1e30f : s[nt][2] * scale;
            s[nt][3] = (diag && c1 > r1) ? -1e30f : s[nt][3] * scale;
        }

        // online softmax
        float mx0 = -1e30f, mx1 = -1e30f;
        #pragma unroll
        for (int nt = 0; nt < 8; nt++) {
            mx0 = fmaxf(mx0, fmaxf(s[nt][0], s[nt][1]));
            mx1 = fmaxf(mx1, fmaxf(s[nt][2], s[nt][3]));
        }
        mx0 = fmaxf(mx0, __shfl_xor_sync(0xffffffffu, mx0, 1));
        mx0 = fmaxf(mx0, __shfl_xor_sync(0xffffffffu, mx0, 2));
        mx1 = fmaxf(mx1, __shfl_xor_sync(0xffffffffu, mx1, 1));
        mx1 = fmaxf(mx1, __shfl_xor_sync(0xffffffffu, mx1, 2));
        float mn0 = fmaxf(m0, mx0), mn1 = fmaxf(m1, mx1);
        float c0f = __expf(m0 - mn0), c1f = __expf(m1 - mn1);
        l0 *= c0f; l1 *= c1f;
        #pragma unroll
        for (int nt = 0; nt < 8; nt++) {
            o[nt][0] *= c0f; o[nt][1] *= c0f;
            o[nt][2] *= c1f; o[nt][3] *= c1f;
        }
        m0 = mn0; m1 = mn1;

        // P -> per-warp private smem rows
        #pragma unroll
        for (int nt = 0; nt < 8; nt++) {
            int c0 = nt * 8 + 2 * lc;
            float p00 = __expf(s[nt][0] - mn0);
            float p01 = __expf(s[nt][1] - mn0);
            float p10 = __expf(s[nt][2] - mn1);
            float p11 = __expf(s[nt][3] - mn1);
            l0 += p00 + p01; l1 += p10 + p11;
            Ps[(wq + lr) * ASd + c0]         = __float_as_uint(p00);
            Ps[(wq + lr) * ASd + c0 + 1]     = __float_as_uint(p01);
            Ps[(wq + lr + 8) * ASd + c0]     = __float_as_uint(p10);
            Ps[(wq + lr + 8) * ASd + c0 + 1] = __float_as_uint(p11);
        }
        __syncwarp();

        // O += P @ V : pa via ldsm.x4 (per ks), bf from Vt via ldsm.x4 (2 ks per load)
        #pragma unroll
        for (int k2 = 0; k2 < 4; k2++) {
            uint32_t paA[4], paB[4];
            ldsm4(paA[0], paA[1], paA[2], paA[3],
                  smem_u32(Ps + (wq + frow) * ASd + (2 * k2) * 8 + fcol));
            ldsm4(paB[0], paB[1], paB[2], paB[3],
                  smem_u32(Ps + (wq + frow) * ASd + (2 * k2 + 1) * 8 + fcol));
            #pragma unroll
            for (int nt = 0; nt < 8; nt++) {
                uint32_t b0, b1, b2, b3;
                ldsm4(b0, b1, b2, b3,
                      smem_u32(Vt + (nt * 8 + brow) * ASd + k2 * 16 + bcol));
                uint32_t bfa[2] = {b0, b1}, bfb[2] = {b2, b3};
                mma_tf32(o[nt], paA, bfa);
                mma_tf32(o[nt], paB, bfb);
            }
        }
        __syncthreads();
    }

    // epilogue
    l0 += __shfl_xor_sync(0xffffffffu, l0, 1);
    l0 += __shfl_xor_sync(0xffffffffu, l0, 2);
    l1 += __shfl_xor_sync(0xffffffffu, l1, 1);
    l1 += __shfl_xor_sync(0xffffffffu, l1, 2);
    float i0 = 1.f / l0, i1 = 1.f / l1;
    int b = bh >> 4, h = bh & 15;
    int row0 = q0 + wq + lr, row1 = row0 + 8;
    float* y0 = Y + (((size_t)(b * Ss + row0)) * Hh + h) * DH;
    float* y1 = Y + (((size_t)(b * Ss + row1)) * Hh + h) * DH;
    #pragma unroll
    for (int nt = 0; nt < 8; nt++) {
        int c = nt * 8 + 2 * lc;
        *(float2*)(y0 + c) = make_float2(o[nt][0] * i0, o[nt][1] * i0);
        *(float2*)(y1 + c) = make_float2(o[nt][2] * i1, o[nt][3] * i1);
    }
}

// ---------------- launch ----------------
extern "C" void kernel_launch(void* const* d_in, const int* in_sizes, int n_in,
                              void* d_out, int out_size) {
    const float* hidden = (const float*)d_in[0];
    const float* ln1_w = (const float*)d_in[2];
    const float* ln1_b = (const float*)d_in[3];
    const float* q_U = (const float*)d_in[4];
    const float* q_V = (const float*)d_in[5];
    const float* q_b = (const float*)d_in[6];
    const float* k_U = (const float*)d_in[7];
    const float* k_V = (const float*)d_in[8];
    const float* k_b = (const float*)d_in[9];
    const float* v_U = (const float*)d_in[10];
    const float* v_V = (const float*)d_in[11];
    const float* v_b = (const float*)d_in[12];
    const float* out_U = (const float*)d_in[13];
    const float* out_V = (const float*)d_in[14];
    const float* out_b = (const float*)d_in[15];
    const float* ln2_w = (const float*)d_in[16];
    const float* ln2_b = (const float*)d_in[17];
    const float* fc1_U = (const float*)d_in[18];
    const float* fc1_V = (const float*)d_in[19];
    const float* fc1_b = (const float*)d_in[20];
    const float* fc2_U = (const float*)d_in[21];
    const float* fc2_V = (const float*)d_in[22];
    const float* fc2_b = (const float*)d_in[23];
    float* out = (float*)d_out;

    float *x_, *Pq_, *Pk_, *Pv_, *Q_, *K_, *V_, *Y_, *t_, *h_, *a_;
    cudaGetSymbolAddress((void**)&x_,  g_x);
    cudaGetSymbolAddress((void**)&Pq_, g_Pq);
    cudaGetSymbolAddress((void**)&Pk_, g_Pk);
    cudaGetSymbolAddress((void**)&Pv_, g_Pv);
    cudaGetSymbolAddress((void**)&Q_,  g_Q);
    cudaGetSymbolAddress((void**)&K_,  g_K);
    cudaGetSymbolAddress((void**)&V_,  g_V);
    cudaGetSymbolAddress((void**)&Y_,  g_Y);
    cudaGetSymbolAddress((void**)&t_,  g_t);
    cudaGetSymbolAddress((void**)&h_,  g_h);
    cudaGetSymbolAddress((void**)&a_,  g_a);

    cudaFuncSetAttribute(attn_mma3, cudaFuncAttributeMaxDynamicSharedMemorySize, ATTN_SMEM);

    // 1) x = LN1(hidden)
    ln_kernel<<<BS, 256>>>(hidden, ln1_w, ln1_b, x_);

    // 2) Pq/Pk/Pv = x @ {q,k,v}_U
    {
        dim3 g(12, BS / 128);
        sgemm_qkv<<<g, 256>>>(x_, q_U, k_U, v_U, Pq_, Pk_, Pv_, BS, HR, Dm);
    }

    // 3) head expansion (V transposed)
    {
        dim3 g(BS / 64, Hh, 3);
        head_proj2<<<g, 256>>>(Pq_, Pk_, Pv_, q_V, k_V, v_V, q_b, k_b, v_b, Q_, K_, V_);
    }

    // 4) causal attention
    {
        dim3 g(Ss / 128, Bb * Hh);
        attn_mma3<<<g, 256, ATTN_SMEM>>>(Q_, K_, V_, Y_);
    }

    // 5) h = hidden + (Y @ out_U) @ out_V + out_b
    {
        dim3 g1(RFC / 64, BS / 128);
        sgemm_t<0, 64><<<g1, 256>>>(Y_, out_U, t_, BS, RFC, Dm, nullptr, nullptr);
        dim3 g2(Dm / 128, BS / 128);
        sgemm_t<1, 128><<<g2, 256>>>(t_, out_V, h_, BS, Dm, RFC, out_b, hidden);
    }

    // 6) z = LN2(h)
    ln_kernel<<<BS, 256>>>(h_, ln2_w, ln2_b, x_);

    // 7) a = gelu((z @ fc1_U) @ fc1_V + fc1_b)
    {
        dim3 g1(RFC / 64, BS / 128);
        sgemm_t<0, 64><<<g1, 256>>>(x_, fc1_U, t_, BS, RFC, Dm, nullptr, nullptr);
        dim3 g2(Ii / 128, BS / 128);
        sgemm_t<2, 128><<<g2, 256>>>(t_, fc1_V, a_, BS, Ii, RFC, fc1_b, nullptr);
    }

    // 8) out = h + (a @ fc2_U) @ fc2_V + fc2_b
    {
        dim3 g1(RFC / 64, BS / 128);
        sgemm_t<0, 64><<<g1, 256>>>(a_, fc2_U, t_, BS, RFC, Ii, nullptr, nullptr);
        dim3 g2(Dm / 128, BS / 128);
        sgemm_t<1, 128><<<g2, 256>>>(t_, fc2_V, out, BS, Dm, RFC, fc2_b, h_);
    }
}

// round 7
// speedup vs baseline: 1.2420x; 1.2358x over previous
#include <cuda_runtime.h>
#include <cuda_bf16.h>
#include <math.h>
#include <stdint.h>

// Problem dims (fixed)
#define Dm   1024
#define Hh   16
#define DH   64
#define Rr   32
#define Bb   2
#define Ss   2048
#define BS   (Bb*Ss)        // 4096
#define HR   (Hh*Rr)        // 512
#define Ii   4096
#define RFC  512

// ---------------- scratch ----------------
__device__ float g_x [BS*Dm];
__device__ float g_Pq[BS*HR];
__device__ float g_Pk[BS*HR];
__device__ float g_Pv[BS*HR];
__device__ float g_Q [Bb*Hh*Ss*DH];
__device__ float g_K [Bb*Hh*Ss*DH];
__device__ float g_V [Bb*Hh*DH*Ss];   // V stored TRANSPOSED: [b,h,dh,s]
__device__ float g_Y [BS*Dm];
__device__ float g_t [BS*RFC];
__device__ float g_h [BS*Dm];
__device__ float g_a [BS*Ii];

// ---------------- PTX helpers ----------------
__device__ __forceinline__ void cp16(uint32_t saddr, const void* gptr) {
    asm volatile("cp.async.ca.shared.global [%0], [%1], 16;" :: "r"(saddr), "l"(gptr));
}
__device__ __forceinline__ uint32_t smem_u32(const void* p) {
    return (uint32_t)__cvta_generic_to_shared(p);
}
__device__ __forceinline__ void ldsm4(uint32_t& r0, uint32_t& r1, uint32_t& r2, uint32_t& r3,
                                      uint32_t addr) {
    asm volatile("ldmatrix.sync.aligned.m8n8.x4.shared.b16 {%0,%1,%2,%3}, [%4];"
                 : "=r"(r0), "=r"(r1), "=r"(r2), "=r"(r3) : "r"(addr));
}
// tf32 mma ignores low 13 mantissa bits: raw fp32 bits are a valid operand.
__device__ __forceinline__ void mma_tf32(float* d, const uint32_t* a, const uint32_t* b) {
    asm volatile(
        "mma.sync.aligned.m16n8k8.row.col.f32.tf32.tf32.f32 "
        "{%0,%1,%2,%3}, {%4,%5,%6,%7}, {%8,%9}, {%0,%1,%2,%3};"
        : "+f"(d[0]), "+f"(d[1]), "+f"(d[2]), "+f"(d[3])
        : "r"(a[0]), "r"(a[1]), "r"(a[2]), "r"(a[3]), "r"(b[0]), "r"(b[1]));
}
__device__ __forceinline__ float gelu_tanh(float x) {
    float u = 0.7978845608f * (x + 0.044715f * x * x * x);
    float t = 1.f - 2.f / (__expf(2.f * u) + 1.f);
    return 0.5f * x * (1.f + t);
}

// ---------------- LayerNorm ----------------
__global__ void ln_kernel(const float* __restrict__ in, const float* __restrict__ w,
                          const float* __restrict__ b, float* __restrict__ out) {
    __shared__ float xs[Dm];
    __shared__ float red[8];
    int row = blockIdx.x;
    int t = threadIdx.x;
    const float* x = in + (size_t)row * Dm;

    float s = 0.f;
    #pragma unroll
    for (int i = t; i < Dm; i += 256) { float v = x[i]; xs[i] = v; s += v; }
    #pragma unroll
    for (int o = 16; o; o >>= 1) s += __shfl_xor_sync(0xffffffffu, s, o);
    if ((t & 31) == 0) red[t >> 5] = s;
    __syncthreads();
    float tot = 0.f;
    #pragma unroll
    for (int i = 0; i < 8; i++) tot += red[i];
    float mean = tot * (1.0f / Dm);
    __syncthreads();

    float vs = 0.f;
    #pragma unroll
    for (int i = t; i < Dm; i += 256) { float d = xs[i] - mean; vs += d * d; }
    #pragma unroll
    for (int o = 16; o; o >>= 1) vs += __shfl_xor_sync(0xffffffffu, vs, o);
    if ((t & 31) == 0) red[t >> 5] = vs;
    __syncthreads();
    float vtot = 0.f;
    #pragma unroll
    for (int i = 0; i < 8; i++) vtot += red[i];
    float rstd = rsqrtf(vtot * (1.0f / Dm) + 1e-5f);

    #pragma unroll
    for (int i = t; i < Dm; i += 256)
        out[(size_t)row * Dm + i] = (xs[i] - mean) * rstd * w[i] + b[i];
}

// ---------------- TF32 GEMM: BK=32, dynamic smem, ldmatrix A-frags ----------------
#define GEMM_BK 32
#define GEMM_AKp 36
#define GEMM_SMEM(BN) ((2 * 128 * GEMM_AKp + 2 * GEMM_BK * ((BN) + 8)) * 4)

template<int EPI, int BN>
__device__ __forceinline__ void gemm_core(
    const float* __restrict__ A, const float* __restrict__ B, float* __restrict__ C,
    int M, int N, int K, const float* __restrict__ bias, const float* __restrict__ res,
    int m0, int n0)
{
    constexpr int BM = 128, BK = GEMM_BK, AKp = GEMM_AKp, BNp = BN + 8;
    constexpr int WM_ = (BN == 128) ? 2 : 4;
    constexpr int WTM = BM / WM_;
    constexpr int WTN = BN / (8 / WM_);
    constexpr int MT = WTM / 16;
    constexpr int NT = WTN / 8;

    extern __shared__ float smf[];
    float* As = smf;                           // [2][BM][AKp]
    float* Bsm = smf + 2 * BM * AKp;           // [2][BK][BNp]

    int tid = threadIdx.x;
    int w = tid >> 5, lane = tid & 31;
    int lr = lane >> 2, lc = lane & 3;
    int wm = (w % WM_) * WTM;
    int wn = (w / WM_) * WTN;
    int arow_f = (lane & 7) + ((lane >> 3) & 1) * 8;
    int acol_f = (lane >> 4) * 4;

    float acc[MT][NT][4];
    #pragma unroll
    for (int mt = 0; mt < MT; mt++)
        #pragma unroll
        for (int nt = 0; nt < NT; nt++)
            #pragma unroll
            for (int i = 0; i < 4; i++) acc[mt][nt][i] = 0.f;

    const float* Ag = A + (size_t)m0 * K;
    const float* Bg = B + n0;

    auto loadTile = [&](int kt, int buf) {
        int k0 = kt * BK;
        float* Abuf = As + buf * BM * AKp;
        float* Bbuf = Bsm + buf * BK * BNp;
        #pragma unroll
        for (int i = 0; i < 4; i++) {              // A: 128x32 = 1024 cp16
            int q = tid + i * 256;
            int m = q >> 3, c = q & 7;
            cp16(smem_u32(Abuf + m * AKp + c * 4), Ag + (size_t)m * K + k0 + c * 4);
        }
        #pragma unroll
        for (int i = 0; i < BN / 32; i++) {        // B: 32xBN
            int q = tid + i * 256;
            int k = q / (BN / 4), n4 = q % (BN / 4);
            cp16(smem_u32(Bbuf + k * BNp + n4 * 4), Bg + (size_t)(k0 + k) * N + n4 * 4);
        }
        asm volatile("cp.async.commit_group;");
    };

    int NTILES = K / BK;
    loadTile(0, 0);
    for (int kt = 0; kt < NTILES; kt++) {
        int buf = kt & 1;
        if (kt + 1 < NTILES) {
            loadTile(kt + 1, buf ^ 1);
            asm volatile("cp.async.wait_group 1;");
        } else {
            asm volatile("cp.async.wait_group 0;");
        }
        __syncthreads();
        const float* Abuf = As + buf * BM * AKp;
        const float* Bbuf = Bsm + buf * BK * BNp;

        #pragma unroll
        for (int ks = 0; ks < 4; ks++) {
            int kb = ks * 8;
            uint32_t af[MT][4], bf[NT][2];
            #pragma unroll
            for (int mt = 0; mt < MT; mt++)
                ldsm4(af[mt][0], af[mt][1], af[mt][2], af[mt][3],
                      smem_u32(Abuf + (wm + mt * 16 + arow_f) * AKp + kb + acol_f));
            #pragma unroll
            for (int nt = 0; nt < NT; nt++) {
                int cn = wn + nt * 8 + lr;
                bf[nt][0] = __float_as_uint(Bbuf[(kb + lc) * BNp + cn]);
                bf[nt][1] = __float_as_uint(Bbuf[(kb + lc + 4) * BNp + cn]);
            }
            #pragma unroll
            for (int mt = 0; mt < MT; mt++)
                #pragma unroll
                for (int nt = 0; nt < NT; nt++)
                    mma_tf32(acc[mt][nt], af[mt], bf[nt]);
        }
        __syncthreads();
    }

    #pragma unroll
    for (int mt = 0; mt < MT; mt++) {
        #pragma unroll
        for (int hh = 0; hh < 2; hh++) {
            int row = m0 + wm + mt * 16 + lr + hh * 8;
            #pragma unroll
            for (int nt = 0; nt < NT; nt++) {
                int col = n0 + wn + nt * 8 + 2 * lc;
                float v0 = acc[mt][nt][2 * hh + 0];
                float v1 = acc[mt][nt][2 * hh + 1];
                if (EPI == 1) {
                    v0 += bias[col]     + res[(size_t)row * N + col];
                    v1 += bias[col + 1] + res[(size_t)row * N + col + 1];
                } else if (EPI == 2) {
                    v0 = gelu_tanh(v0 + bias[col]);
                    v1 = gelu_tanh(v1 + bias[col + 1]);
                }
                *(float2*)&C[(size_t)row * N + col] = make_float2(v0, v1);
            }
        }
    }
}

template<int EPI, int BN>
__global__ void __launch_bounds__(256, 2) sgemm_t(
    const float* __restrict__ A, const float* __restrict__ B, float* __restrict__ C,
    int M, int N, int K, const float* __restrict__ bias, const float* __restrict__ res)
{
    gemm_core<EPI, BN>(A, B, C, M, N, K, bias, res, blockIdx.y * 128, blockIdx.x * BN);
}

__global__ void __launch_bounds__(256, 2) sgemm_qkv(
    const float* __restrict__ A,
    const float* __restrict__ B0, const float* __restrict__ B1, const float* __restrict__ B2,
    float* __restrict__ C0, float* __restrict__ C1, float* __restrict__ C2,
    int M, int N, int K)
{
    int sel = blockIdx.x >> 2, nb = blockIdx.x & 3;
    const float* B = (sel == 0) ? B0 : (sel == 1) ? B1 : B2;
    float* C = (sel == 0) ? C0 : (sel == 1) ? C1 : C2;
    gemm_core<0, 128>(A, B, C, M, N, K, nullptr, nullptr, blockIdx.y * 128, nb * 128);
}

// ---------------- head_proj: q,k -> (b,h,s,e); v -> TRANSPOSED (b,h,e,s) ----------------
__global__ void __launch_bounds__(256) head_proj2(
    const float* __restrict__ Pq, const float* __restrict__ Pk, const float* __restrict__ Pv,
    const float* __restrict__ Vq, const float* __restrict__ Vk, const float* __restrict__ Vv,
    const float* __restrict__ bq, const float* __restrict__ bk, const float* __restrict__ bv,
    float* __restrict__ Oq, float* __restrict__ Ok, float* __restrict__ Ov)
{
    __shared__ float vw[Rr][DH];
    __shared__ float pt[64][Rr + 1];
    int z = blockIdx.z;
    const float* P  = (z == 0) ? Pq : (z == 1) ? Pk : Pv;
    const float* Vw = (z == 0) ? Vq : (z == 1) ? Vk : Vv;
    const float* bi = (z == 0) ? bq : (z == 1) ? bk : bv;
    float* O        = (z == 0) ? Oq : (z == 1) ? Ok : Ov;

    int h = blockIdx.y;
    int s0 = blockIdx.x * 64;
    int tid = threadIdx.x;

    #pragma unroll
    for (int i = 0; i < 8; i++) {
        int idx = tid + i * 256;
        vw[idx >> 6][idx & 63] = Vw[(size_t)h * Rr * DH + idx];
    }
    #pragma unroll
    for (int i = 0; i < 8; i++) {
        int idx = tid + i * 256;
        int r = idx >> 5, c = idx & 31;
        pt[r][c] = P[(size_t)(s0 + r) * HR + h * Rr + c];
    }
    __syncthreads();

    if (z < 2) {
        int e = tid & 63;
        int sl = tid >> 6;
        float bv_ = bi[h * DH + e];
        #pragma unroll
        for (int i = 0; i < 16; i++) {
            int r = sl + i * 4;
            float acc = bv_;
            #pragma unroll
            for (int rr = 0; rr < Rr; rr++) acc = fmaf(pt[r][rr], vw[rr][e], acc);
            int bs = s0 + r;
            int b = bs >> 11, s = bs & 2047;
            O[(((size_t)(b * Hh + h)) * Ss + s) * DH + e] = acc;
        }
    } else {
        int sl = tid & 63;
        int e0 = tid >> 6;
        int bs = s0 + sl;
        int b = bs >> 11, s = bs & 2047;
        float* obase = O + ((size_t)(b * Hh + h)) * DH * Ss + s;
        #pragma unroll
        for (int i = 0; i < 16; i++) {
            int e = e0 + i * 4;
            float acc = bi[h * DH + e];
            #pragma unroll
            for (int rr = 0; rr < Rr; rr++) acc = fmaf(pt[sl][rr], vw[rr][e], acc);
            obase[(size_t)e * Ss] = acc;
        }
    }
}

// ---------------- attention v5: single-buffer + ldmatrix + 2 CTA/SM ----------------
#define ASd 68
#define ATTN_SMEM ((64 * ASd + 64 * ASd + 128 * ASd) * 4)   // 69632 B

__global__ void __launch_bounds__(256, 2) attn_mma4(
    const float* __restrict__ Q, const float* __restrict__ K,
    const float* __restrict__ V, float* __restrict__ Y)
{
    extern __shared__ uint32_t sm[];
    uint32_t* Ks = sm;                    // [64][ASd]
    uint32_t* Vt = sm + 64 * ASd;         // [64][ASd]  (V transposed: [dh][s])
    uint32_t* Ps = sm + 128 * ASd;        // [128][ASd]

    int bh = blockIdx.y;
    int qblk = gridDim.x - 1 - blockIdx.x;   // heavy blocks first
    int q0 = qblk * 128;
    int tid = threadIdx.x;
    int w = tid >> 5, lane = tid & 31;
    int lr = lane >> 2, lc = lane & 3;
    int wq = w * 16;
    int frow = (lane & 7) + ((lane >> 3) & 1) * 8;   // A-frag ldsm row-in-16
    int fcol = (lane >> 4) * 4;                       // A-frag ldsm col chunk
    int brow = lane & 7;                              // B-frag ldsm row-in-8
    int bcol = (lane >> 3) * 4;                       // B-frag ldsm col chunk

    // persistent Q fragments (raw fp32 bits)
    uint32_t qf[8][4];
    const float* Qb = Q + ((size_t)bh * Ss + q0 + wq) * DH;
    #pragma unroll
    for (int ks = 0; ks < 8; ks++) {
        qf[ks][0] = __float_as_uint(Qb[(size_t)lr * DH + ks * 8 + lc]);
        qf[ks][1] = __float_as_uint(Qb[(size_t)(lr + 8) * DH + ks * 8 + lc]);
        qf[ks][2] = __float_as_uint(Qb[(size_t)lr * DH + ks * 8 + lc + 4]);
        qf[ks][3] = __float_as_uint(Qb[(size_t)(lr + 8) * DH + ks * 8 + lc + 4]);
    }

    const float* Kg = K + (size_t)bh * Ss * DH;
    const float* Vg = V + (size_t)bh * DH * Ss;

    float o[8][4];
    #pragma unroll
    for (int nt = 0; nt < 8; nt++)
        #pragma unroll
        for (int i = 0; i < 4; i++) o[nt][i] = 0.f;
    float m0 = -1e30f, m1 = -1e30f, l0 = 0.f, l1 = 0.f;
    const float scale = 0.125f;

    int ktmax = 2 * qblk + 1;
    for (int kt = 0; kt <= ktmax; kt++) {
        __syncthreads();                      // prior tile fully consumed
        #pragma unroll
        for (int i = 0; i < 4; i++) {
            int idx = tid + i * 256;
            int r = idx >> 4, c4 = (idx & 15) * 4;
            cp16(smem_u32(Ks + r * ASd + c4), Kg + (size_t)(kt * 64 + r) * DH + c4);
            cp16(smem_u32(Vt + r * ASd + c4), Vg + (size_t)r * Ss + kt * 64 + c4);
        }
        asm volatile("cp.async.commit_group;");
        asm volatile("cp.async.wait_group 0;");
        __syncthreads();

        // S = Q @ K^T (per warp 16x64)
        float s[8][4];
        #pragma unroll
        for (int nt = 0; nt < 8; nt++)
            #pragma unroll
            for (int i = 0; i < 4; i++) s[nt][i] = 0.f;
        #pragma unroll
        for (int k2 = 0; k2 < 4; k2++) {
            #pragma unroll
            for (int nt = 0; nt < 8; nt++) {
                uint32_t b0, b1, b2, b3;
                ldsm4(b0, b1, b2, b3,
                      smem_u32(Ks + (nt * 8 + brow) * ASd + k2 * 16 + bcol));
                uint32_t bfa[2] = {b0, b1}, bfb[2] = {b2, b3};
                mma_tf32(s[nt], qf[2 * k2],     bfa);
                mma_tf32(s[nt], qf[2 * k2 + 1], bfb);
            }
        }

        // scale + causal mask
        bool diag = (kt >= 2 * qblk);
        int r0 = q0 + wq + lr, r1 = r0 + 8;
        int kc0 = kt * 64;
        #pragma unroll
        for (int nt = 0; nt < 8; nt++) {
            int c0 = kc0 + nt * 8 + 2 * lc, c1 = c0 + 1;
            s[nt][0] = (diag && c0 > r0) ? -1e30f : s[nt][0] * scale;
            s[nt][1] = (diag && c1 > r0) ? -1e30f : s[nt][1] * scale;
            s[nt][2] = (diag && c0 > r1) ? -1e30f : s[nt][2] * scale;
            s[nt][3] = (diag && c1 > r1) ? -1e30f : s[nt][3] * scale;
        }

        // online softmax
        float mx0 = -1e30f, mx1 = -1e30f;
        #pragma unroll
        for (int nt = 0; nt < 8; nt++) {
            mx0 = fmaxf(mx0, fmaxf(s[nt][0], s[nt][1]));
            mx1 = fmaxf(mx1, fmaxf(s[nt][2], s[nt][3]));
        }
        mx0 = fmaxf(mx0, __shfl_xor_sync(0xffffffffu, mx0, 1));
        mx0 = fmaxf(mx0, __shfl_xor_sync(0xffffffffu, mx0, 2));
        mx1 = fmaxf(mx1, __shfl_xor_sync(0xffffffffu, mx1, 1));
        mx1 = fmaxf(mx1, __shfl_xor_sync(0xffffffffu, mx1, 2));
        float mn0 = fmaxf(m0, mx0), mn1 = fmaxf(m1, mx1);
        float c0f = __expf(m0 - mn0), c1f = __expf(m1 - mn1);
        l0 *= c0f; l1 *= c1f;
        #pragma unroll
        for (int nt = 0; nt < 8; nt++) {
            o[nt][0] *= c0f; o[nt][1] *= c0f;
            o[nt][2] *= c1f; o[nt][3] *= c1f;
        }
        m0 = mn0; m1 = mn1;

        // P -> per-warp private smem rows
        #pragma unroll
        for (int nt = 0; nt < 8; nt++) {
            int c0 = nt * 8 + 2 * lc;
            float p00 = __expf(s[nt][0] - mn0);
            float p01 = __expf(s[nt][1] - mn0);
            float p10 = __expf(s[nt][2] - mn1);
            float p11 = __expf(s[nt][3] - mn1);
            l0 += p00 + p01; l1 += p10 + p11;
            Ps[(wq + lr) * ASd + c0]         = __float_as_uint(p00);
            Ps[(wq + lr) * ASd + c0 + 1]     = __float_as_uint(p01);
            Ps[(wq + lr + 8) * ASd + c0]     = __float_as_uint(p10);
            Ps[(wq + lr + 8) * ASd + c0 + 1] = __float_as_uint(p11);
        }
        __syncwarp();

        // O += P @ V
        #pragma unroll
        for (int k2 = 0; k2 < 4; k2++) {
            uint32_t paA[4], paB[4];
            ldsm4(paA[0], paA[1], paA[2], paA[3],
                  smem_u32(Ps + (wq + frow) * ASd + (2 * k2) * 8 + fcol));
            ldsm4(paB[0], paB[1], paB[2], paB[3],
                  smem_u32(Ps + (wq + frow) * ASd + (2 * k2 + 1) * 8 + fcol));
            #pragma unroll
            for (int nt = 0; nt < 8; nt++) {
                uint32_t b0, b1, b2, b3;
                ldsm4(b0, b1, b2, b3,
                      smem_u32(Vt + (nt * 8 + brow) * ASd + k2 * 16 + bcol));
                uint32_t bfa[2] = {b0, b1}, bfb[2] = {b2, b3};
                mma_tf32(o[nt], paA, bfa);
                mma_tf32(o[nt], paB, bfb);
            }
        }
    }

    // epilogue
    l0 += __shfl_xor_sync(0xffffffffu, l0, 1);
    l0 += __shfl_xor_sync(0xffffffffu, l0, 2);
    l1 += __shfl_xor_sync(0xffffffffu, l1, 1);
    l1 += __shfl_xor_sync(0xffffffffu, l1, 2);
    float i0 = 1.f / l0, i1 = 1.f / l1;
    int b = bh >> 4, h = bh & 15;
    int row0 = q0 + wq + lr, row1 = row0 + 8;
    float* y0 = Y + (((size_t)(b * Ss + row0)) * Hh + h) * DH;
    float* y1 = Y + (((size_t)(b * Ss + row1)) * Hh + h) * DH;
    #pragma unroll
    for (int nt = 0; nt < 8; nt++) {
        int c = nt * 8 + 2 * lc;
        *(float2*)(y0 + c) = make_float2(o[nt][0] * i0, o[nt][1] * i0);
        *(float2*)(y1 + c) = make_float2(o[nt][2] * i1, o[nt][3] * i1);
    }
}

// ---------------- launch ----------------
extern "C" void kernel_launch(void* const* d_in, const int* in_sizes, int n_in,
                              void* d_out, int out_size) {
    const float* hidden = (const float*)d_in[0];
    const float* ln1_w = (const float*)d_in[2];
    const float* ln1_b = (const float*)d_in[3];
    const float* q_U = (const float*)d_in[4];
    const float* q_V = (const float*)d_in[5];
    const float* q_b = (const float*)d_in[6];
    const float* k_U = (const float*)d_in[7];
    const float* k_V = (const float*)d_in[8];
    const float* k_b = (const float*)d_in[9];
    const float* v_U = (const float*)d_in[10];
    const float* v_V = (const float*)d_in[11];
    const float* v_b = (const float*)d_in[12];
    const float* out_U = (const float*)d_in[13];
    const float* out_V = (const float*)d_in[14];
    const float* out_b = (const float*)d_in[15];
    const float* ln2_w = (const float*)d_in[16];
    const float* ln2_b = (const float*)d_in[17];
    const float* fc1_U = (const float*)d_in[18];
    const float* fc1_V = (const float*)d_in[19];
    const float* fc1_b = (const float*)d_in[20];
    const float* fc2_U = (const float*)d_in[21];
    const float* fc2_V = (const float*)d_in[22];
    const float* fc2_b = (const float*)d_in[23];
    float* out = (float*)d_out;

    float *x_, *Pq_, *Pk_, *Pv_, *Q_, *K_, *V_, *Y_, *t_, *h_, *a_;
    cudaGetSymbolAddress((void**)&x_,  g_x);
    cudaGetSymbolAddress((void**)&Pq_, g_Pq);
    cudaGetSymbolAddress((void**)&Pk_, g_Pk);
    cudaGetSymbolAddress((void**)&Pv_, g_Pv);
    cudaGetSymbolAddress((void**)&Q_,  g_Q);
    cudaGetSymbolAddress((void**)&K_,  g_K);
    cudaGetSymbolAddress((void**)&V_,  g_V);
    cudaGetSymbolAddress((void**)&Y_,  g_Y);
    cudaGetSymbolAddress((void**)&t_,  g_t);
    cudaGetSymbolAddress((void**)&h_,  g_h);
    cudaGetSymbolAddress((void**)&a_,  g_a);

    cudaFuncSetAttribute(attn_mma4, cudaFuncAttributeMaxDynamicSharedMemorySize, ATTN_SMEM);
    cudaFuncSetAttribute(sgemm_qkv, cudaFuncAttributeMaxDynamicSharedMemorySize, GEMM_SMEM(128));
    cudaFuncSetAttribute(sgemm_t<0, 64>,  cudaFuncAttributeMaxDynamicSharedMemorySize, GEMM_SMEM(64));
    cudaFuncSetAttribute(sgemm_t<1, 128>, cudaFuncAttributeMaxDynamicSharedMemorySize, GEMM_SMEM(128));
    cudaFuncSetAttribute(sgemm_t<2, 128>, cudaFuncAttributeMaxDynamicSharedMemorySize, GEMM_SMEM(128));

    // 1) x = LN1(hidden)
    ln_kernel<<<BS, 256>>>(hidden, ln1_w, ln1_b, x_);

    // 2) Pq/Pk/Pv = x @ {q,k,v}_U
    {
        dim3 g(12, BS / 128);
        sgemm_qkv<<<g, 256, GEMM_SMEM(128)>>>(x_, q_U, k_U, v_U, Pq_, Pk_, Pv_, BS, HR, Dm);
    }

    // 3) head expansion (V transposed)
    {
        dim3 g(BS / 64, Hh, 3);
        head_proj2<<<g, 256>>>(Pq_, Pk_, Pv_, q_V, k_V, v_V, q_b, k_b, v_b, Q_, K_, V_);
    }

    // 4) causal attention
    {
        dim3 g(Ss / 128, Bb * Hh);
        attn_mma4<<<g, 256, ATTN_SMEM>>>(Q_, K_, V_, Y_);
    }

    // 5) h = hidden + (Y @ out_U) @ out_V + out_b
    {
        dim3 g1(RFC / 64, BS / 128);
        sgemm_t<0, 64><<<g1, 256, GEMM_SMEM(64)>>>(Y_, out_U, t_, BS, RFC, Dm, nullptr, nullptr);
        dim3 g2(Dm / 128, BS / 128);
        sgemm_t<1, 128><<<g2, 256, GEMM_SMEM(128)>>>(t_, out_V, h_, BS, Dm, RFC, out_b, hidden);
    }

    // 6) z = LN2(h)
    ln_kernel<<<BS, 256>>>(h_, ln2_w, ln2_b, x_);

    // 7) a = gelu((z @ fc1_U) @ fc1_V + fc1_b)
    {
        dim3 g1(RFC / 64, BS / 128);
        sgemm_t<0, 64><<<g1, 256, GEMM_SMEM(64)>>>(x_, fc1_U, t_, BS, RFC, Dm, nullptr, nullptr);
        dim3 g2(Ii / 128, BS / 128);
        sgemm_t<2, 128><<<g2, 256, GEMM_SMEM(128)>>>(t_, fc1_V, a_, BS, Ii, RFC, fc1_b, nullptr);
    }

    // 8) out = h + (a @ fc2_U) @ fc2_V + fc2_b
    {
        dim3 g1(RFC / 64, BS / 128);
        sgemm_t<0, 64><<<g1, 256, GEMM_SMEM(64)>>>(a_, fc2_U, t_, BS, RFC, Ii, nullptr, nullptr);
        dim3 g2(Dm / 128, BS / 128);
        sgemm_t<1, 128><<<g2, 256, GEMM_SMEM(128)>>>(t_, fc2_V, out, BS, Dm, RFC, fc2_b, h_);
    }
}